// round 13
// baseline (speedup 1.0000x reference)
#include <cuda_runtime.h>

#define T_STEPS 10
#define B_SZ    32
#define CIN     3
#define COUT    64
#define SPAT    4096            // 64*64
#define N_THR   (T_STEPS * COUT)
#define DECAY   0.2f
#define INH     1.625f
#define KC      4.6166241f      /* 3.2 * log2(e) */

// Scratch: conv results, CHANNEL-LAST layout (t, b, sp, c).  335.5 MB
__device__ float    g_i[T_STEPS * B_SZ * SPAT * COUT];
__device__ unsigned g_thr_keys[N_THR];   // zero-init at load; self-reset each run
__device__ float4   g_thrv[N_THR];       // {thr, INH*thr, 8*log2e/thr, 0}

// ---------------------------------------------------------------------------
// Conv 3x3, stride 1, pad 1. LANE = CHANNEL-PAIR with register weights and a
// sliding 3x3x3 input window; float2 stores -> coalesced channel-last output.
// R13: 256-thread blocks (8 warps, 32x32 tile) for 2 blocks/SM occupancy.
#define STEP(S0_, S1_, S2_, C_, DOLOAD_) do {                                 \
    float a0 = 0.f, a1 = 0.f, a2 = 0.f, b0 = 0.f, b1 = 0.f, b2 = 0.f;         \
    const int SL_[3] = {S0_, S1_, S2_};                                       \
    _Pragma("unroll")                                                         \
    for (int ky = 0; ky < 3; ky++)                                            \
        _Pragma("unroll")                                                     \
        for (int kx = 0; kx < 3; kx++) {                                      \
            const int j = ky * 3 + kx;                                        \
            const int s = SL_[kx];                                            \
            a0 = fmaf(xw[0][s][ky], w0[j],      a0);                          \
            a1 = fmaf(xw[1][s][ky], w0[j + 9],  a1);                          \
            a2 = fmaf(xw[2][s][ky], w0[j + 18], a2);                          \
            b0 = fmaf(xw[0][s][ky], w1[j],      b0);                          \
            b1 = fmaf(xw[1][s][ky], w1[j + 9],  b1);                          \
            b2 = fmaf(xw[2][s][ky], w1[j + 18], b2);                          \
        }                                                                     \
    const float v0 = (a0 + a1) + a2;                                          \
    const float v1 = (b0 + b1) + b2;                                          \
    gp[sprow + (C_) * 32 + tx] = make_float2(v0, v1);                         \
    mx0 = fmaxf(mx0, v0);                                                     \
    mx1 = fmaxf(mx1, v1);                                                     \
    if (DOLOAD_) {                                                            \
        _Pragma("unroll")                                                     \
        for (int ci = 0; ci < CIN; ci++)                                      \
            _Pragma("unroll")                                                 \
            for (int ky = 0; ky < 3; ky++)                                    \
                xw[ci][S0_][ky] = xs[ci][row + ky][(C_) + 3];                 \
    }                                                                         \
} while (0)

__global__ void __launch_bounds__(256, 2) conv_kernel(const float* __restrict__ x,
                                                      const float* __restrict__ Wt) {
    __shared__ float    xs[CIN][34][34];     // 32x32 tile + halo
    __shared__ float    ws[COUT * 28];       // 27 weights + 1 pad per channel
    __shared__ unsigned smax[COUT][8];       // per-warp max keys

    const int tb  = blockIdx.z;              // t*B + b
    const int t   = tb >> 5;
    const int tx  = threadIdx.x;             // lane -> channels 2tx, 2tx+1
    const int wid = threadIdx.y;             // 8 warps -> 8 row groups
    const int tid = wid * 32 + tx;

    for (int idx = tid; idx < COUT * 27; idx += 256) {
        int co = idx / 27;
        ws[co * 28 + (idx - co * 27)] = Wt[idx];
    }

    const float* xb = x + tb * (CIN * SPAT);
    const int y0 = blockIdx.y * 32;
    const int x0 = blockIdx.x * 32;
    for (int idx = tid; idx < CIN * 1156; idx += 256) {
        int ci  = idx / 1156;
        int rem = idx - ci * 1156;
        int yy  = rem / 34;
        int xx  = rem - yy * 34;
        int gy = y0 + yy - 1, gx = x0 + xx - 1;
        float v = 0.f;
        if ((unsigned)gy < 64u && (unsigned)gx < 64u) v = xb[ci * SPAT + gy * 64 + gx];
        xs[ci][yy][xx] = v;
    }
    __syncthreads();

    float w0[28], w1[28];
    {
        const float4* p0 = (const float4*)(ws + (2 * tx) * 28);
        const float4* p1 = (const float4*)(ws + (2 * tx + 1) * 28);
#pragma unroll
        for (int q = 0; q < 7; q++) {
            float4 a = p0[q];
            w0[4 * q] = a.x; w0[4 * q + 1] = a.y; w0[4 * q + 2] = a.z; w0[4 * q + 3] = a.w;
            float4 c = p1[q];
            w1[4 * q] = c.x; w1[4 * q + 1] = c.y; w1[4 * q + 2] = c.z; w1[4 * q + 3] = c.w;
        }
    }

    float2* gp = (float2*)g_i + (long)tb * (SPAT * 32);
    float mx0 = -1e30f, mx1 = -1e30f;

#pragma unroll 1
    for (int rr = 0; rr < 4; rr++) {
        const int row = 4 * wid + rr;                       // tile row 0..31
        const int sprow = ((y0 + row) * 64 + x0) * 32;      // float2 base

        float xw[CIN][3][3];                                // [ci][slot][ky]
#pragma unroll
        for (int ci = 0; ci < CIN; ci++)
#pragma unroll
            for (int s = 0; s < 3; s++)
#pragma unroll
                for (int ky = 0; ky < 3; ky++)
                    xw[ci][s][ky] = xs[ci][row + ky][s];

#pragma unroll 1
        for (int c3 = 0; c3 < 30; c3 += 3) {
            STEP(0, 1, 2, c3 + 0, true);
            STEP(1, 2, 0, c3 + 1, true);
            STEP(2, 0, 1, c3 + 2, true);
        }
        STEP(0, 1, 2, 30, true);     // loads col 33 into slot 0
        STEP(1, 2, 0, 31, false);
    }

    unsigned u0 = __float_as_uint(mx0);
    unsigned k0 = ((int)u0 < 0) ? ~u0 : (u0 | 0x80000000u);
    unsigned u1 = __float_as_uint(mx1);
    unsigned k1 = ((int)u1 < 0) ? ~u1 : (u1 | 0x80000000u);
    smax[2 * tx][wid]     = k0;
    smax[2 * tx + 1][wid] = k1;
    __syncthreads();
    if (tid < COUT) {
        unsigned m = smax[tid][0];
#pragma unroll
        for (int wdi = 1; wdi < 8; wdi++) m = max(m, smax[tid][wdi]);
        atomicMax(&g_thr_keys[t * COUT + tid], m);
    }
}

// ---------------------------------------------------------------------------
// Decode per-(t,c) max keys -> threshold vectors, then RESET the keys so the
// next graph replay starts from zero.
__global__ void finalize_thr() {
    int i = blockIdx.x * blockDim.x + threadIdx.x;
    if (i < N_THR) {
        unsigned k = g_thr_keys[i];
        unsigned u = (k & 0x80000000u) ? (k & 0x7FFFFFFFu) : ~k;
        float thr  = __uint_as_float(u) + 1e-4f;
        float zs   = 11.541560f / thr;        // 8*log2(e)/thr
        g_thrv[i]  = make_float4(thr, INH * thr, zs, 0.f);
        g_thr_keys[i] = 0u;                   // self-reset for next replay
    }
}

// ---------------------------------------------------------------------------
// LIF + ASF + WTA + inhibition (R10/R12, proven): warp-per-pixel on
// channel-last data, lane owns channels 2tx/2tx+1 (one coalesced float2 load
// per t), WTA via 2 REDUX ops, mem in regs. No barriers in the t-loop.
__global__ void __launch_bounds__(1024) lif_kernel(float* __restrict__ out) {
    __shared__ float2 sth[320], sih[320], szs[320];  // [t*32 + pair]
    __shared__ int    swz[32][11];                   // [pixel][t], pad 11

    const int tx  = threadIdx.x;         // lane -> channel pair
    const int ty  = threadIdx.y;         // warp -> pixel
    const int tid = ty * 32 + tx;
    const int b   = blockIdx.x >> 7;     // 128 blocks per batch image
    const int spb = (blockIdx.x & 127) * 32;

    if (tid < 320) {
        int t = tid >> 5, p = tid & 31;
        float4 a = g_thrv[t * COUT + 2 * p];
        float4 c = g_thrv[t * COUT + 2 * p + 1];
        sth[tid] = make_float2(a.x, c.x);
        sih[tid] = make_float2(a.y, c.y);
        szs[tid] = make_float2(a.z, c.z);
    }
    __syncthreads();

    const int sp    = spb + ty;
    const int c0    = 2 * tx, c1 = 2 * tx + 1;
    const float2* ip = (const float2*)g_i;
    const int pbase = (b * SPAT + sp) * 32 + tx;     // float2 index
    const int tstep = B_SZ * SPAT * 32;              // float2 per timestep

    float2 b0 = ip[pbase];
    float2 b1 = ip[pbase + tstep];
    float m0 = 0.f, m1 = 0.f;

#pragma unroll
    for (int t = 0; t < T_STEPS; t++) {
        const float2 iv = (t & 1) ? b1 : b0;
        if (t + 2 < T_STEPS) {                       // depth-2 prefetch
            if (t & 1) b1 = ip[pbase + (t + 2) * tstep];
            else       b0 = ip[pbase + (t + 2) * tstep];
        }
        const float2 th = sth[t * 32 + tx];
        const float2 ih = sih[t * 32 + tx];
        const float2 zs = szs[t * 32 + tx];

        // fast ASF: thr / (1 + exp2(KC - cur*zs))
        float zn0 = fmaf(fmaxf(iv.x, 0.f), -zs.x, KC);
        float zn1 = fmaf(fmaxf(iv.y, 0.f), -zs.y, KC);
        float e0, e1, q0, q1;
        asm("ex2.approx.f32 %0, %1;" : "=f"(e0) : "f"(zn0));
        asm("ex2.approx.f32 %0, %1;" : "=f"(e1) : "f"(zn1));
        asm("rcp.approx.f32 %0, %1;" : "=f"(q0) : "f"(1.f + e0));
        asm("rcp.approx.f32 %0, %1;" : "=f"(q1) : "f"(1.f + e1));

        m0 = fmaf(m0, DECAY, th.x * q0);
        m1 = fmaf(m1, DECAY, th.y * q1);

        const int   s0i = m0 > th.x ? 1 : 0;
        const int   s1i = m1 > th.y ? 1 : 0;
        const float sc0 = s0i ? m0 : 0.f;
        const float sc1 = s1i ? m1 : 0.f;

        // per-lane candidate; lower channel wins ties (argmax-first semantics)
        float bs; int bi;
        if (sc0 >= sc1) { bs = sc0; bi = (c0 << 1) | s0i; }
        else            { bs = sc1; bi = (c1 << 1) | s1i; }

        unsigned ub   = __float_as_uint(bs);
        unsigned key  = ((int)ub < 0) ? ~ub : (ub | 0x80000000u);
        unsigned mk   = __reduce_max_sync(0xffffffffu, key);
        unsigned cand = (key == mk) ? (unsigned)bi : 0x7fffffffu;
        const int wz  = (int)__reduce_min_sync(0xffffffffu, cand);

        const int   wc  = wz >> 1;
        const float any = (float)(wz & 1);            // winner's spike -> any_sp

        const float sn0 = (wc == c0) ? (float)s0i : 0.f;
        const float sn1 = (wc == c1) ? (float)s1i : 0.f;

        m0 = (sn0 > 0.f) ? 0.f : fmaf(-ih.x, any, m0);
        m1 = (sn1 > 0.f) ? 0.f : fmaf(-ih.y, any, m1);

        if (tx == 0) swz[ty][t] = wz;
    }
    __syncthreads();

    // store phase: reference layout (t,b,c,h,w); lanes = pixels (coalesced)
    const int obase = (b * COUT) * SPAT + spb + tx;
    const int ostep = B_SZ * COUT * SPAT;
#pragma unroll
    for (int t = 0; t < T_STEPS; t++) {
        const int w = swz[tx][t];
        out[obase + t * ostep + ty * SPAT]        = (w == ((ty << 1) | 1))        ? 1.f : 0.f;
        out[obase + t * ostep + (ty + 32) * SPAT] = (w == (((ty + 32) << 1) | 1)) ? 1.f : 0.f;
    }
}

// ---------------------------------------------------------------------------
extern "C" void kernel_launch(void* const* d_in, const int* in_sizes, int n_in,
                              void* d_out, int out_size) {
    const float* x = (const float*)d_in[0];
    const float* W = (const float*)d_in[1];
    if (n_in >= 2 && in_sizes[0] == COUT * CIN * 9) {  // defensive order swap
        const float* tmp = x; x = W; W = tmp;
    }

    dim3 cb(32, 8);
    dim3 cg(2, 2, T_STEPS * B_SZ);
    conv_kernel<<<cg, cb>>>(x, W);

    finalize_thr<<<1, N_THR>>>();

    lif_kernel<<<(B_SZ * SPAT) / 32, dim3(32, 32)>>>((float*)d_out);
}

// round 14
// speedup vs baseline: 1.1294x; 1.1294x over previous
#include <cuda_runtime.h>

#define T_STEPS 10
#define B_SZ    32
#define CIN     3
#define COUT    64
#define SPAT    4096            // 64*64
#define N_THR   (T_STEPS * COUT)
#define DECAY   0.2f
#define INH     1.625f
#define KC      4.6166241f      /* 3.2 * log2(e) */

// Scratch: conv results, CHANNEL-LAST layout (t, b, sp, c).  335.5 MB
__device__ float    g_i[T_STEPS * B_SZ * SPAT * COUT];
__device__ unsigned g_thr_keys[N_THR];   // zero-init at load; self-reset each run
__device__ float4   g_thrv[N_THR];       // {thr, INH*thr, 8*log2e/thr, 0}

// ---- packed f32x2 add (2-operand: rt=2, exact per-component IEEE rn) ------
__device__ __forceinline__ unsigned long long add2(unsigned long long a,
                                                   unsigned long long b) {
    unsigned long long d;
    asm("add.rn.f32x2 %0, %1, %2;" : "=l"(d) : "l"(a), "l"(b));
    return d;
}
__device__ __forceinline__ void upk2(unsigned long long v, float& lo, float& hi) {
    asm("mov.b64 {%0,%1}, %2;" : "=f"(lo), "=f"(hi) : "l"(v));
}

// ---------------------------------------------------------------------------
// Conv 3x3, stride 1, pad 1 exploiting BINARY input: each pixel's 3 input
// bits form a code 0..7; W8[tap][code][co] pre-sums the weights so the inner
// loop is 9 table lookups + 8 packed adds per output pair (no FMAs at all).
// Every product is exactly w or 0 -> only association order differs from fp32
// FMA conv (ulp-scale). Lane = channel pair; float2 stores stay channel-last.

// Table lookup: byte offset off into W8 (8B aligned)
#define TBL64(off) (*(const unsigned long long*)((const char*)W8 + (off)))

// Slot S0_ holds codes for kx=0 (imm -4096), S1_ kx=1 (-2048), S2_ kx=2 (0).
// Loads column C_+2 codes into S2_ first, then sums 9 taps (fixed tree),
// stores float2, tracks per-channel max.
#define STEP2(S0_, S1_, S2_, C_) do {                                         \
    aoff[S2_][0] = (int)code16[row + 0][(C_) + 2] + lc0;                      \
    aoff[S2_][1] = (int)code16[row + 1][(C_) + 2] + lc1;                      \
    aoff[S2_][2] = (int)code16[row + 2][(C_) + 2] + lc2;                      \
    unsigned long long t0_ = TBL64(aoff[S0_][0] - 4096);                      \
    unsigned long long t1_ = TBL64(aoff[S1_][0] - 2048);                      \
    unsigned long long t2_ = TBL64(aoff[S2_][0]);                             \
    unsigned long long t3_ = TBL64(aoff[S0_][1] - 4096);                      \
    unsigned long long t4_ = TBL64(aoff[S1_][1] - 2048);                      \
    unsigned long long t5_ = TBL64(aoff[S2_][1]);                             \
    unsigned long long t6_ = TBL64(aoff[S0_][2] - 4096);                      \
    unsigned long long t7_ = TBL64(aoff[S1_][2] - 2048);                      \
    unsigned long long t8_ = TBL64(aoff[S2_][2]);                             \
    unsigned long long s_ = add2(add2(add2(t0_, t1_), add2(t2_, t3_)),        \
                                 add2(add2(t4_, t5_), add2(t6_, t7_)));       \
    s_ = add2(s_, t8_);                                                       \
    float v0_, v1_;                                                           \
    upk2(s_, v0_, v1_);                                                       \
    gp[sprow + (C_) * 32 + tx] = make_float2(v0_, v1_);                       \
    mx0 = fmaxf(mx0, v0_);                                                    \
    mx1 = fmaxf(mx1, v1_);                                                    \
} while (0)

__global__ void __launch_bounds__(128) conv_kernel(const float* __restrict__ x,
                                                   const float* __restrict__ Wt) {
    __shared__ __align__(16) float W8[9 * 8 * COUT];   // 18 KB: [tap][code][co]
    __shared__ float            ws[COUT * 27];         // raw weights
    __shared__ unsigned short   code16[18][36];        // code*256, halo'd tile
    __shared__ unsigned         smax[COUT][4];

    const int tb  = blockIdx.z;              // t*B + b
    const int t   = tb >> 5;
    const int tx  = threadIdx.x;             // lane -> channels 2tx, 2tx+1
    const int wid = threadIdx.y;             // 4 warps -> 4 row groups
    const int tid = wid * 32 + tx;

    // phase A: raw weights + input code plane
    for (int idx = tid; idx < COUT * 27; idx += 128) ws[idx] = Wt[idx];

    const float* xb = x + tb * (CIN * SPAT);
    const int y0 = blockIdx.y * 16;
    const int x0 = blockIdx.x * 32;
    for (int idx = tid; idx < 18 * 34; idx += 128) {
        int yy = idx / 34;
        int xx = idx - yy * 34;
        int gy = y0 + yy - 1, gx = x0 + xx - 1;
        unsigned short code = 0;
        if ((unsigned)gy < 64u && (unsigned)gx < 64u) {
            const int o = gy * 64 + gx;
            int c = (xb[o] != 0.f ? 1 : 0) | (xb[SPAT + o] != 0.f ? 2 : 0)
                  | (xb[2 * SPAT + o] != 0.f ? 4 : 0);
            code = (unsigned short)(c << 8);             // pre-scaled *256B
        }
        code16[yy][xx] = code;
    }
    __syncthreads();

    // phase B: build W8[tap*512 + code*64 + co] = sum of selected weights
    for (int e = tid; e < 9 * 8 * COUT; e += 128) {
        const int tap  = e >> 9;
        const int code = (e >> 6) & 7;
        const int co   = e & 63;
        const float wa = ws[co * 27 + tap];
        const float wb = ws[co * 27 + 9 + tap];
        const float wc = ws[co * 27 + 18 + tap];
        float v = ((code & 1) ? wa : 0.f) + ((code & 2) ? wb : 0.f);
        v += ((code & 4) ? wc : 0.f);
        W8[e] = v;
    }
    __syncthreads();

    // lane constants: channel offset + ky tap-row offset + kx=2 fold (+4096)
    const int lc0 = tx * 8 + 4096;
    const int lc1 = tx * 8 + 6144 + 4096;
    const int lc2 = tx * 8 + 12288 + 4096;

    float2* gp = (float2*)g_i + (long)tb * (SPAT * 32);
    float mx0 = -1e30f, mx1 = -1e30f;

#pragma unroll 1
    for (int rr = 0; rr < 4; rr++) {
        const int row = 4 * wid + rr;                       // tile row 0..15
        const int sprow = ((y0 + row) * 64 + x0) * 32;      // float2 base

        int aoff[3][3];                                     // [slot][ky]
        aoff[0][0] = (int)code16[row + 0][0] + lc0;
        aoff[0][1] = (int)code16[row + 1][0] + lc1;
        aoff[0][2] = (int)code16[row + 2][0] + lc2;
        aoff[1][0] = (int)code16[row + 0][1] + lc0;
        aoff[1][1] = (int)code16[row + 1][1] + lc1;
        aoff[1][2] = (int)code16[row + 2][1] + lc2;

#pragma unroll 1
        for (int c3 = 0; c3 < 30; c3 += 3) {
            STEP2(0, 1, 2, c3 + 0);
            STEP2(1, 2, 0, c3 + 1);
            STEP2(2, 0, 1, c3 + 2);
        }
        STEP2(0, 1, 2, 30);
        STEP2(1, 2, 0, 31);
    }

    // per-(t,c) max: order-preserving keys, block reduce, one global atomic
    unsigned u0 = __float_as_uint(mx0);
    unsigned k0 = ((int)u0 < 0) ? ~u0 : (u0 | 0x80000000u);
    unsigned u1 = __float_as_uint(mx1);
    unsigned k1 = ((int)u1 < 0) ? ~u1 : (u1 | 0x80000000u);
    smax[2 * tx][wid]     = k0;
    smax[2 * tx + 1][wid] = k1;
    __syncthreads();
    if (tid < COUT) {
        unsigned m = smax[tid][0];
        m = max(m, smax[tid][1]); m = max(m, smax[tid][2]); m = max(m, smax[tid][3]);
        atomicMax(&g_thr_keys[t * COUT + tid], m);
    }
}

// ---------------------------------------------------------------------------
// Decode per-(t,c) max keys -> threshold vectors, then RESET the keys so the
// next graph replay starts from zero.
__global__ void finalize_thr() {
    int i = blockIdx.x * blockDim.x + threadIdx.x;
    if (i < N_THR) {
        unsigned k = g_thr_keys[i];
        unsigned u = (k & 0x80000000u) ? (k & 0x7FFFFFFFu) : ~k;
        float thr  = __uint_as_float(u) + 1e-4f;
        float zs   = 11.541560f / thr;        // 8*log2(e)/thr
        g_thrv[i]  = make_float4(thr, INH * thr, zs, 0.f);
        g_thr_keys[i] = 0u;                   // self-reset for next replay
    }
}

// ---------------------------------------------------------------------------
// LIF + ASF + WTA + inhibition (R10/R12, proven): warp-per-pixel on
// channel-last data, lane owns channels 2tx/2tx+1 (one coalesced float2 load
// per t), WTA via 2 REDUX ops, mem in regs. No barriers in the t-loop.
__global__ void __launch_bounds__(1024) lif_kernel(float* __restrict__ out) {
    __shared__ float2 sth[320], sih[320], szs[320];  // [t*32 + pair]
    __shared__ int    swz[32][11];                   // [pixel][t], pad 11

    const int tx  = threadIdx.x;         // lane -> channel pair
    const int ty  = threadIdx.y;         // warp -> pixel
    const int tid = ty * 32 + tx;
    const int b   = blockIdx.x >> 7;     // 128 blocks per batch image
    const int spb = (blockIdx.x & 127) * 32;

    if (tid < 320) {
        int t = tid >> 5, p = tid & 31;
        float4 a = g_thrv[t * COUT + 2 * p];
        float4 c = g_thrv[t * COUT + 2 * p + 1];
        sth[tid] = make_float2(a.x, c.x);
        sih[tid] = make_float2(a.y, c.y);
        szs[tid] = make_float2(a.z, c.z);
    }
    __syncthreads();

    const int sp    = spb + ty;
    const int c0    = 2 * tx, c1 = 2 * tx + 1;
    const float2* ip = (const float2*)g_i;
    const int pbase = (b * SPAT + sp) * 32 + tx;     // float2 index
    const int tstep = B_SZ * SPAT * 32;              // float2 per timestep

    float2 b0 = ip[pbase];
    float2 b1 = ip[pbase + tstep];
    float m0 = 0.f, m1 = 0.f;

#pragma unroll
    for (int t = 0; t < T_STEPS; t++) {
        const float2 iv = (t & 1) ? b1 : b0;
        if (t + 2 < T_STEPS) {                       // depth-2 prefetch
            if (t & 1) b1 = ip[pbase + (t + 2) * tstep];
            else       b0 = ip[pbase + (t + 2) * tstep];
        }
        const float2 th = sth[t * 32 + tx];
        const float2 ih = sih[t * 32 + tx];
        const float2 zs = szs[t * 32 + tx];

        // fast ASF: thr / (1 + exp2(KC - cur*zs))
        float zn0 = fmaf(fmaxf(iv.x, 0.f), -zs.x, KC);
        float zn1 = fmaf(fmaxf(iv.y, 0.f), -zs.y, KC);
        float e0, e1, q0, q1;
        asm("ex2.approx.f32 %0, %1;" : "=f"(e0) : "f"(zn0));
        asm("ex2.approx.f32 %0, %1;" : "=f"(e1) : "f"(zn1));
        asm("rcp.approx.f32 %0, %1;" : "=f"(q0) : "f"(1.f + e0));
        asm("rcp.approx.f32 %0, %1;" : "=f"(q1) : "f"(1.f + e1));

        m0 = fmaf(m0, DECAY, th.x * q0);
        m1 = fmaf(m1, DECAY, th.y * q1);

        const int   s0i = m0 > th.x ? 1 : 0;
        const int   s1i = m1 > th.y ? 1 : 0;
        const float sc0 = s0i ? m0 : 0.f;
        const float sc1 = s1i ? m1 : 0.f;

        // per-lane candidate; lower channel wins ties (argmax-first semantics)
        float bs; int bi;
        if (sc0 >= sc1) { bs = sc0; bi = (c0 << 1) | s0i; }
        else            { bs = sc1; bi = (c1 << 1) | s1i; }

        unsigned ub   = __float_as_uint(bs);
        unsigned key  = ((int)ub < 0) ? ~ub : (ub | 0x80000000u);
        unsigned mk   = __reduce_max_sync(0xffffffffu, key);
        unsigned cand = (key == mk) ? (unsigned)bi : 0x7fffffffu;
        const int wz  = (int)__reduce_min_sync(0xffffffffu, cand);

        const int   wc  = wz >> 1;
        const float any = (float)(wz & 1);            // winner's spike -> any_sp

        const float sn0 = (wc == c0) ? (float)s0i : 0.f;
        const float sn1 = (wc == c1) ? (float)s1i : 0.f;

        m0 = (sn0 > 0.f) ? 0.f : fmaf(-ih.x, any, m0);
        m1 = (sn1 > 0.f) ? 0.f : fmaf(-ih.y, any, m1);

        if (tx == 0) swz[ty][t] = wz;
    }
    __syncthreads();

    // store phase: reference layout (t,b,c,h,w); lanes = pixels (coalesced)
    const int obase = (b * COUT) * SPAT + spb + tx;
    const int ostep = B_SZ * COUT * SPAT;
#pragma unroll
    for (int t = 0; t < T_STEPS; t++) {
        const int w = swz[tx][t];
        out[obase + t * ostep + ty * SPAT]        = (w == ((ty << 1) | 1))        ? 1.f : 0.f;
        out[obase + t * ostep + (ty + 32) * SPAT] = (w == (((ty + 32) << 1) | 1)) ? 1.f : 0.f;
    }
}

// ---------------------------------------------------------------------------
extern "C" void kernel_launch(void* const* d_in, const int* in_sizes, int n_in,
                              void* d_out, int out_size) {
    const float* x = (const float*)d_in[0];
    const float* W = (const float*)d_in[1];
    if (n_in >= 2 && in_sizes[0] == COUT * CIN * 9) {  // defensive order swap
        const float* tmp = x; x = W; W = tmp;
    }

    dim3 cb(32, 4);
    dim3 cg(2, 4, T_STEPS * B_SZ);
    conv_kernel<<<cg, cb>>>(x, W);

    finalize_thr<<<1, N_THR>>>();

    lif_kernel<<<(B_SZ * SPAT) / 32, dim3(32, 32)>>>((float*)d_out);
}

// round 15
// speedup vs baseline: 1.2198x; 1.0801x over previous
#include <cuda_runtime.h>

#define T_STEPS 10
#define B_SZ    32
#define CIN     3
#define COUT    64
#define SPAT    4096            // 64*64
#define N_THR   (T_STEPS * COUT)
#define DECAY   0.2f
#define INH     1.625f
#define KC      4.6166241f      /* 3.2 * log2(e) */

// Scratch: conv results, CHANNEL-LAST layout (t, b, sp, c).  335.5 MB
__device__ float    g_i[T_STEPS * B_SZ * SPAT * COUT];
__device__ unsigned g_thr_keys[N_THR];   // zero-init at load; self-reset each run
__device__ float4   g_thrv[N_THR];       // {thr, INH*thr, 8*log2e/thr, 0}

// ---- packed f32x2 add (2-operand: rt=2, exact per-component IEEE rn) ------
__device__ __forceinline__ unsigned long long add2(unsigned long long a,
                                                   unsigned long long b) {
    unsigned long long d;
    asm("add.rn.f32x2 %0, %1, %2;" : "=l"(d) : "l"(a), "l"(b));
    return d;
}
__device__ __forceinline__ void upk2(unsigned long long v, float& lo, float& hi) {
    asm("mov.b64 {%0,%1}, %2;" : "=f"(lo), "=f"(hi) : "l"(v));
}

// ---------------------------------------------------------------------------
// Conv 3x3, stride 1, pad 1 exploiting BINARY input: pixel code 0..7 indexes
// W8[tap][code][co] (pre-summed weights); inner loop is up to 9 table lookups
// + 8 packed adds per output pair. R15: lookups are PREDICATED on code != 0
// (warp-uniform, ~51% of pixels) -> ~2x fewer smem wavefronts, bit-exact
// (skipped entries are exactly +0.0, add tree unchanged).

// Table lookup: byte offset off into W8 (8B aligned)
#define TBL64(off) (*(const unsigned long long*)((const char*)W8 + (off)))

// cz[slot][ky] holds code*256 (byte offset into a tap's 8-code group).
// Slot S0_ -> kx=0, S1_ -> kx=1, S2_ -> kx=2. Tap (ky,kx) byte base =
// lp + kx*2048 + ky*6144, lp = tx*8 (channel pair).
#define STEP2(S0_, S1_, S2_, C_) do {                                         \
    cz[S2_][0] = (int)code16[row + 0][(C_) + 2];                              \
    cz[S2_][1] = (int)code16[row + 1][(C_) + 2];                              \
    cz[S2_][2] = (int)code16[row + 2][(C_) + 2];                              \
    unsigned long long t0_ = 0ull, t1_ = 0ull, t2_ = 0ull, t3_ = 0ull,        \
                       t4_ = 0ull, t5_ = 0ull, t6_ = 0ull, t7_ = 0ull,        \
                       t8_ = 0ull;                                            \
    if (cz[S0_][0]) t0_ = TBL64(cz[S0_][0] + lp);                             \
    if (cz[S1_][0]) t1_ = TBL64(cz[S1_][0] + lp + 2048);                      \
    if (cz[S2_][0]) t2_ = TBL64(cz[S2_][0] + lp + 4096);                      \
    if (cz[S0_][1]) t3_ = TBL64(cz[S0_][1] + lp + 6144);                      \
    if (cz[S1_][1]) t4_ = TBL64(cz[S1_][1] + lp + 8192);                      \
    if (cz[S2_][1]) t5_ = TBL64(cz[S2_][1] + lp + 10240);                     \
    if (cz[S0_][2]) t6_ = TBL64(cz[S0_][2] + lp + 12288);                     \
    if (cz[S1_][2]) t7_ = TBL64(cz[S1_][2] + lp + 14336);                     \
    if (cz[S2_][2]) t8_ = TBL64(cz[S2_][2] + lp + 16384);                     \
    unsigned long long s_ = add2(add2(add2(t0_, t1_), add2(t2_, t3_)),        \
                                 add2(add2(t4_, t5_), add2(t6_, t7_)));       \
    s_ = add2(s_, t8_);                                                       \
    float v0_, v1_;                                                           \
    upk2(s_, v0_, v1_);                                                       \
    gp[sprow + (C_) * 32 + tx] = make_float2(v0_, v1_);                       \
    mx0 = fmaxf(mx0, v0_);                                                    \
    mx1 = fmaxf(mx1, v1_);                                                    \
} while (0)

__global__ void __launch_bounds__(128) conv_kernel(const float* __restrict__ x,
                                                   const float* __restrict__ Wt) {
    __shared__ __align__(16) float W8[9 * 8 * COUT];   // 18 KB: [tap][code][co]
    __shared__ float            ws[COUT * 27];         // raw weights
    __shared__ unsigned short   code16[18][36];        // code*256, halo'd tile
    __shared__ unsigned         smax[COUT][4];

    const int tb  = blockIdx.z;              // t*B + b
    const int t   = tb >> 5;
    const int tx  = threadIdx.x;             // lane -> channels 2tx, 2tx+1
    const int wid = threadIdx.y;             // 4 warps -> 4 row groups
    const int tid = wid * 32 + tx;

    // phase A: raw weights + input code plane
    for (int idx = tid; idx < COUT * 27; idx += 128) ws[idx] = Wt[idx];

    const float* xb = x + tb * (CIN * SPAT);
    const int y0 = blockIdx.y * 16;
    const int x0 = blockIdx.x * 32;
    for (int idx = tid; idx < 18 * 34; idx += 128) {
        int yy = idx / 34;
        int xx = idx - yy * 34;
        int gy = y0 + yy - 1, gx = x0 + xx - 1;
        unsigned short code = 0;
        if ((unsigned)gy < 64u && (unsigned)gx < 64u) {
            const int o = gy * 64 + gx;
            int c = (xb[o] != 0.f ? 1 : 0) | (xb[SPAT + o] != 0.f ? 2 : 0)
                  | (xb[2 * SPAT + o] != 0.f ? 4 : 0);
            code = (unsigned short)(c << 8);             // pre-scaled *256B
        }
        code16[yy][xx] = code;
    }
    __syncthreads();

    // phase B: build W8[tap*512 + code*64 + co] = sum of selected weights
    for (int e = tid; e < 9 * 8 * COUT; e += 128) {
        const int tap  = e >> 9;
        const int code = (e >> 6) & 7;
        const int co   = e & 63;
        const float wa = ws[co * 27 + tap];
        const float wb = ws[co * 27 + 9 + tap];
        const float wc = ws[co * 27 + 18 + tap];
        float v = ((code & 1) ? wa : 0.f) + ((code & 2) ? wb : 0.f);
        v += ((code & 4) ? wc : 0.f);
        W8[e] = v;
    }
    __syncthreads();

    const int lp = tx * 8;                   // channel-pair byte offset

    float2* gp = (float2*)g_i + (long)tb * (SPAT * 32);
    float mx0 = -1e30f, mx1 = -1e30f;

#pragma unroll 1
    for (int rr = 0; rr < 4; rr++) {
        const int row = 4 * wid + rr;                       // tile row 0..15
        const int sprow = ((y0 + row) * 64 + x0) * 32;      // float2 base

        int cz[3][3];                                       // [slot][ky], code*256
        cz[0][0] = (int)code16[row + 0][0];
        cz[0][1] = (int)code16[row + 1][0];
        cz[0][2] = (int)code16[row + 2][0];
        cz[1][0] = (int)code16[row + 0][1];
        cz[1][1] = (int)code16[row + 1][1];
        cz[1][2] = (int)code16[row + 2][1];

#pragma unroll 1
        for (int c3 = 0; c3 < 30; c3 += 3) {
            STEP2(0, 1, 2, c3 + 0);
            STEP2(1, 2, 0, c3 + 1);
            STEP2(2, 0, 1, c3 + 2);
        }
        STEP2(0, 1, 2, 30);
        STEP2(1, 2, 0, 31);
    }

    // per-(t,c) max: order-preserving keys, block reduce, one global atomic
    unsigned u0 = __float_as_uint(mx0);
    unsigned k0 = ((int)u0 < 0) ? ~u0 : (u0 | 0x80000000u);
    unsigned u1 = __float_as_uint(mx1);
    unsigned k1 = ((int)u1 < 0) ? ~u1 : (u1 | 0x80000000u);
    smax[2 * tx][wid]     = k0;
    smax[2 * tx + 1][wid] = k1;
    __syncthreads();
    if (tid < COUT) {
        unsigned m = smax[tid][0];
        m = max(m, smax[tid][1]); m = max(m, smax[tid][2]); m = max(m, smax[tid][3]);
        atomicMax(&g_thr_keys[t * COUT + tid], m);
    }
}

// ---------------------------------------------------------------------------
// Decode per-(t,c) max keys -> threshold vectors, then RESET the keys so the
// next graph replay starts from zero.
__global__ void finalize_thr() {
    int i = blockIdx.x * blockDim.x + threadIdx.x;
    if (i < N_THR) {
        unsigned k = g_thr_keys[i];
        unsigned u = (k & 0x80000000u) ? (k & 0x7FFFFFFFu) : ~k;
        float thr  = __uint_as_float(u) + 1e-4f;
        float zs   = 11.541560f / thr;        // 8*log2(e)/thr
        g_thrv[i]  = make_float4(thr, INH * thr, zs, 0.f);
        g_thr_keys[i] = 0u;                   // self-reset for next replay
    }
}

// ---------------------------------------------------------------------------
// LIF + ASF + WTA + inhibition (R10/R12, proven): warp-per-pixel on
// channel-last data, lane owns channels 2tx/2tx+1 (one coalesced float2 load
// per t), WTA via 2 REDUX ops, mem in regs. No barriers in the t-loop.
__global__ void __launch_bounds__(1024) lif_kernel(float* __restrict__ out) {
    __shared__ float2 sth[320], sih[320], szs[320];  // [t*32 + pair]
    __shared__ int    swz[32][11];                   // [pixel][t], pad 11

    const int tx  = threadIdx.x;         // lane -> channel pair
    const int ty  = threadIdx.y;         // warp -> pixel
    const int tid = ty * 32 + tx;
    const int b   = blockIdx.x >> 7;     // 128 blocks per batch image
    const int spb = (blockIdx.x & 127) * 32;

    if (tid < 320) {
        int t = tid >> 5, p = tid & 31;
        float4 a = g_thrv[t * COUT + 2 * p];
        float4 c = g_thrv[t * COUT + 2 * p + 1];
        sth[tid] = make_float2(a.x, c.x);
        sih[tid] = make_float2(a.y, c.y);
        szs[tid] = make_float2(a.z, c.z);
    }
    __syncthreads();

    const int sp    = spb + ty;
    const int c0    = 2 * tx, c1 = 2 * tx + 1;
    const float2* ip = (const float2*)g_i;
    const int pbase = (b * SPAT + sp) * 32 + tx;     // float2 index
    const int tstep = B_SZ * SPAT * 32;              // float2 per timestep

    float2 b0 = ip[pbase];
    float2 b1 = ip[pbase + tstep];
    float m0 = 0.f, m1 = 0.f;

#pragma unroll
    for (int t = 0; t < T_STEPS; t++) {
        const float2 iv = (t & 1) ? b1 : b0;
        if (t + 2 < T_STEPS) {                       // depth-2 prefetch
            if (t & 1) b1 = ip[pbase + (t + 2) * tstep];
            else       b0 = ip[pbase + (t + 2) * tstep];
        }
        const float2 th = sth[t * 32 + tx];
        const float2 ih = sih[t * 32 + tx];
        const float2 zs = szs[t * 32 + tx];

        // fast ASF: thr / (1 + exp2(KC - cur*zs))
        float zn0 = fmaf(fmaxf(iv.x, 0.f), -zs.x, KC);
        float zn1 = fmaf(fmaxf(iv.y, 0.f), -zs.y, KC);
        float e0, e1, q0, q1;
        asm("ex2.approx.f32 %0, %1;" : "=f"(e0) : "f"(zn0));
        asm("ex2.approx.f32 %0, %1;" : "=f"(e1) : "f"(zn1));
        asm("rcp.approx.f32 %0, %1;" : "=f"(q0) : "f"(1.f + e0));
        asm("rcp.approx.f32 %0, %1;" : "=f"(q1) : "f"(1.f + e1));

        m0 = fmaf(m0, DECAY, th.x * q0);
        m1 = fmaf(m1, DECAY, th.y * q1);

        const int   s0i = m0 > th.x ? 1 : 0;
        const int   s1i = m1 > th.y ? 1 : 0;
        const float sc0 = s0i ? m0 : 0.f;
        const float sc1 = s1i ? m1 : 0.f;

        // per-lane candidate; lower channel wins ties (argmax-first semantics)
        float bs; int bi;
        if (sc0 >= sc1) { bs = sc0; bi = (c0 << 1) | s0i; }
        else            { bs = sc1; bi = (c1 << 1) | s1i; }

        unsigned ub   = __float_as_uint(bs);
        unsigned key  = ((int)ub < 0) ? ~ub : (ub | 0x80000000u);
        unsigned mk   = __reduce_max_sync(0xffffffffu, key);
        unsigned cand = (key == mk) ? (unsigned)bi : 0x7fffffffu;
        const int wz  = (int)__reduce_min_sync(0xffffffffu, cand);

        const int   wc  = wz >> 1;
        const float any = (float)(wz & 1);            // winner's spike -> any_sp

        const float sn0 = (wc == c0) ? (float)s0i : 0.f;
        const float sn1 = (wc == c1) ? (float)s1i : 0.f;

        m0 = (sn0 > 0.f) ? 0.f : fmaf(-ih.x, any, m0);
        m1 = (sn1 > 0.f) ? 0.f : fmaf(-ih.y, any, m1);

        if (tx == 0) swz[ty][t] = wz;
    }
    __syncthreads();

    // store phase: reference layout (t,b,c,h,w); lanes = pixels (coalesced)
    const int obase = (b * COUT) * SPAT + spb + tx;
    const int ostep = B_SZ * COUT * SPAT;
#pragma unroll
    for (int t = 0; t < T_STEPS; t++) {
        const int w = swz[tx][t];
        out[obase + t * ostep + ty * SPAT]        = (w == ((ty << 1) | 1))        ? 1.f : 0.f;
        out[obase + t * ostep + (ty + 32) * SPAT] = (w == (((ty + 32) << 1) | 1)) ? 1.f : 0.f;
    }
}

// ---------------------------------------------------------------------------
extern "C" void kernel_launch(void* const* d_in, const int* in_sizes, int n_in,
                              void* d_out, int out_size) {
    const float* x = (const float*)d_in[0];
    const float* W = (const float*)d_in[1];
    if (n_in >= 2 && in_sizes[0] == COUT * CIN * 9) {  // defensive order swap
        const float* tmp = x; x = W; W = tmp;
    }

    dim3 cb(32, 4);
    dim3 cg(2, 4, T_STEPS * B_SZ);
    conv_kernel<<<cg, cb>>>(x, W);

    finalize_thr<<<1, N_THR>>>();

    lif_kernel<<<(B_SZ * SPAT) / 32, dim3(32, 32)>>>((float*)d_out);
}

// round 16
// speedup vs baseline: 1.2738x; 1.0443x over previous
#include <cuda_runtime.h>

#define T_STEPS 10
#define B_SZ    32
#define CIN     3
#define COUT    64
#define SPAT    4096            // 64*64
#define N_THR   (T_STEPS * COUT)
#define DECAY   0.2f
#define INH     1.625f
#define KC      4.6166241f      /* 3.2 * log2(e) */

// Scratch: conv results, CHANNEL-LAST layout (t, b, sp, c).  335.5 MB
__device__ float    g_i[T_STEPS * B_SZ * SPAT * COUT];
__device__ unsigned g_thr_keys[N_THR];   // zero-init at load; self-reset each run
__device__ float4   g_thrv[N_THR];       // {thr, INH*thr, 8*log2e/thr, 0}

// ---- packed f32x2 add (2-operand: rt=2, exact per-component IEEE rn) ------
__device__ __forceinline__ unsigned long long add2(unsigned long long a,
                                                   unsigned long long b) {
    unsigned long long d;
    asm("add.rn.f32x2 %0, %1, %2;" : "=l"(d) : "l"(a), "l"(b));
    return d;
}
__device__ __forceinline__ void upk2(unsigned long long v, float& lo, float& hi) {
    asm("mov.b64 {%0,%1}, %2;" : "=f"(lo), "=f"(hi) : "l"(v));
}

// ---------------------------------------------------------------------------
// Conv 3x3, stride 1, pad 1, binary-input table conv (R15) with PACKED CODE
// REGISTERS: tile-row codes live in u64 bitfields (8 codes x 8b per u64), so
// the inner loop extracts codes with 2 ALU ops instead of LDS.U16 -> ~22%
// fewer smem wavefronts. Lookups stay predicated on code!=0 (bit-exact:
// skipped entries are +0.0; add tree unchanged from R14/R15).

#define TBL64(off) (*(const unsigned long long*)((const char*)W8 + (off)))

__global__ void __launch_bounds__(128) conv_kernel(const float* __restrict__ x,
                                                   const float* __restrict__ Wt) {
    __shared__ __align__(16) float W8[9 * 8 * COUT];   // 18 KB: [tap][code][co]
    __shared__ float              ws[COUT * 27];       // raw weights
    __shared__ unsigned char      codep[18][36];       // plain codes 0..7
    __shared__ unsigned long long crow[18][6];         // packed: 8 codes/u64
    __shared__ unsigned           smax[COUT][4];

    const int tb  = blockIdx.z;              // t*B + b
    const int t   = tb >> 5;
    const int tx  = threadIdx.x;             // lane -> channels 2tx, 2tx+1
    const int wid = threadIdx.y;             // 4 warps -> 4 row groups
    const int tid = wid * 32 + tx;

    // phase A: raw weights + plain code plane
    for (int idx = tid; idx < COUT * 27; idx += 128) ws[idx] = Wt[idx];

    const float* xb = x + tb * (CIN * SPAT);
    const int y0 = blockIdx.y * 16;
    const int x0 = blockIdx.x * 32;
    for (int idx = tid; idx < 18 * 34; idx += 128) {
        int yy = idx / 34;
        int xx = idx - yy * 34;
        int gy = y0 + yy - 1, gx = x0 + xx - 1;
        unsigned char code = 0;
        if ((unsigned)gy < 64u && (unsigned)gx < 64u) {
            const int o = gy * 64 + gx;
            code = (unsigned char)((xb[o] != 0.f ? 1 : 0)
                 | (xb[SPAT + o] != 0.f ? 2 : 0)
                 | (xb[2 * SPAT + o] != 0.f ? 4 : 0));
        }
        codep[yy][xx] = code;
    }
    __syncthreads();

    // phase B: W8 table + packed code rows
    for (int e = tid; e < 9 * 8 * COUT; e += 128) {
        const int tap  = e >> 9;
        const int code = (e >> 6) & 7;
        const int co   = e & 63;
        const float wa = ws[co * 27 + tap];
        const float wb = ws[co * 27 + 9 + tap];
        const float wc = ws[co * 27 + 18 + tap];
        float v = ((code & 1) ? wa : 0.f) + ((code & 2) ? wb : 0.f);
        v += ((code & 4) ? wc : 0.f);
        W8[e] = v;
    }
    for (int e = tid; e < 18 * 6; e += 128) {
        const int yy = e / 6, g = e - (e / 6) * 6;
        unsigned long long v = 0ull;
#pragma unroll
        for (int j = 0; j < 8; j++) {
            const int col = 8 * g + j;
            if (col < 34) v |= (unsigned long long)codep[yy][col] << (8 * j);
        }
        crow[yy][g] = v;
    }
    __syncthreads();

    const int lp = tx * 8;                   // channel-pair byte offset

    float2* gp = (float2*)g_i + (long)tb * (SPAT * 32);
    float mx0 = -1e30f, mx1 = -1e30f;

#pragma unroll 1
    for (int rr = 0; rr < 4; rr++) {
        const int row = 4 * wid + rr;                       // tile row 0..15
        const int sprow = ((y0 + row) * 64 + x0) * 32;      // float2 base

        unsigned long long r0[3], r1[3];
#pragma unroll
        for (int k = 0; k < 3; k++) {
            r0[k] = crow[row + k][0];
            r1[k] = crow[row + k][1];
        }

#pragma unroll 1
        for (int blk = 0; blk < 4; blk++) {
            unsigned long long r2[3];
#pragma unroll
            for (int k = 0; k < 3; k++) r2[k] = crow[row + k][blk + 2];

#pragma unroll
            for (int j = 0; j < 8; j++) {
                const int C = blk * 8 + j;
                // extract the 9 tap codes (compile-time shifts; CSE across j)
                int cz[9];
#pragma unroll
                for (int ky = 0; ky < 3; ky++)
#pragma unroll
                    for (int kx = 0; kx < 3; kx++) {
                        const int cc = j + kx;
                        const unsigned long long w = (cc < 8) ? r0[ky] : r1[ky];
                        const int sh = (cc & 7) * 8;
                        cz[ky * 3 + kx] = ((int)(w >> sh) & 7) << 8;
                    }
                unsigned long long t0_ = 0ull, t1_ = 0ull, t2_ = 0ull,
                                   t3_ = 0ull, t4_ = 0ull, t5_ = 0ull,
                                   t6_ = 0ull, t7_ = 0ull, t8_ = 0ull;
                if (cz[0]) t0_ = TBL64(cz[0] + lp);
                if (cz[1]) t1_ = TBL64(cz[1] + lp + 2048);
                if (cz[2]) t2_ = TBL64(cz[2] + lp + 4096);
                if (cz[3]) t3_ = TBL64(cz[3] + lp + 6144);
                if (cz[4]) t4_ = TBL64(cz[4] + lp + 8192);
                if (cz[5]) t5_ = TBL64(cz[5] + lp + 10240);
                if (cz[6]) t6_ = TBL64(cz[6] + lp + 12288);
                if (cz[7]) t7_ = TBL64(cz[7] + lp + 14336);
                if (cz[8]) t8_ = TBL64(cz[8] + lp + 16384);
                unsigned long long s_ =
                    add2(add2(add2(t0_, t1_), add2(t2_, t3_)),
                         add2(add2(t4_, t5_), add2(t6_, t7_)));
                s_ = add2(s_, t8_);
                float v0_, v1_;
                upk2(s_, v0_, v1_);
                gp[sprow + C * 32 + tx] = make_float2(v0_, v1_);
                mx0 = fmaxf(mx0, v0_);
                mx1 = fmaxf(mx1, v1_);
            }
#pragma unroll
            for (int k = 0; k < 3; k++) { r0[k] = r1[k]; r1[k] = r2[k]; }
        }
    }

    // per-(t,c) max: order-preserving keys, block reduce, one global atomic
    unsigned u0 = __float_as_uint(mx0);
    unsigned k0 = ((int)u0 < 0) ? ~u0 : (u0 | 0x80000000u);
    unsigned u1 = __float_as_uint(mx1);
    unsigned k1 = ((int)u1 < 0) ? ~u1 : (u1 | 0x80000000u);
    smax[2 * tx][wid]     = k0;
    smax[2 * tx + 1][wid] = k1;
    __syncthreads();
    if (tid < COUT) {
        unsigned m = smax[tid][0];
        m = max(m, smax[tid][1]); m = max(m, smax[tid][2]); m = max(m, smax[tid][3]);
        atomicMax(&g_thr_keys[t * COUT + tid], m);
    }
}

// ---------------------------------------------------------------------------
// Decode per-(t,c) max keys -> threshold vectors, then RESET the keys so the
// next graph replay starts from zero.
__global__ void finalize_thr() {
    int i = blockIdx.x * blockDim.x + threadIdx.x;
    if (i < N_THR) {
        unsigned k = g_thr_keys[i];
        unsigned u = (k & 0x80000000u) ? (k & 0x7FFFFFFFu) : ~k;
        float thr  = __uint_as_float(u) + 1e-4f;
        float zs   = 11.541560f / thr;        // 8*log2(e)/thr
        g_thrv[i]  = make_float4(thr, INH * thr, zs, 0.f);
        g_thr_keys[i] = 0u;                   // self-reset for next replay
    }
}

// ---------------------------------------------------------------------------
// LIF + ASF + WTA + inhibition (R10/R12, proven): warp-per-pixel on
// channel-last data, lane owns channels 2tx/2tx+1 (one coalesced float2 load
// per t), WTA via 2 REDUX ops, mem in regs. No barriers in the t-loop.
__global__ void __launch_bounds__(1024) lif_kernel(float* __restrict__ out) {
    __shared__ float2 sth[320], sih[320], szs[320];  // [t*32 + pair]
    __shared__ int    swz[32][11];                   // [pixel][t], pad 11

    const int tx  = threadIdx.x;         // lane -> channel pair
    const int ty  = threadIdx.y;         // warp -> pixel
    const int tid = ty * 32 + tx;
    const int b   = blockIdx.x >> 7;     // 128 blocks per batch image
    const int spb = (blockIdx.x & 127) * 32;

    if (tid < 320) {
        int t = tid >> 5, p = tid & 31;
        float4 a = g_thrv[t * COUT + 2 * p];
        float4 c = g_thrv[t * COUT + 2 * p + 1];
        sth[tid] = make_float2(a.x, c.x);
        sih[tid] = make_float2(a.y, c.y);
        szs[tid] = make_float2(a.z, c.z);
    }
    __syncthreads();

    const int sp    = spb + ty;
    const int c0    = 2 * tx, c1 = 2 * tx + 1;
    const float2* ip = (const float2*)g_i;
    const int pbase = (b * SPAT + sp) * 32 + tx;     // float2 index
    const int tstep = B_SZ * SPAT * 32;              // float2 per timestep

    float2 b0 = ip[pbase];
    float2 b1 = ip[pbase + tstep];
    float m0 = 0.f, m1 = 0.f;

#pragma unroll
    for (int t = 0; t < T_STEPS; t++) {
        const float2 iv = (t & 1) ? b1 : b0;
        if (t + 2 < T_STEPS) {                       // depth-2 prefetch
            if (t & 1) b1 = ip[pbase + (t + 2) * tstep];
            else       b0 = ip[pbase + (t + 2) * tstep];
        }
        const float2 th = sth[t * 32 + tx];
        const float2 ih = sih[t * 32 + tx];
        const float2 zs = szs[t * 32 + tx];

        // fast ASF: thr / (1 + exp2(KC - cur*zs))
        float zn0 = fmaf(fmaxf(iv.x, 0.f), -zs.x, KC);
        float zn1 = fmaf(fmaxf(iv.y, 0.f), -zs.y, KC);
        float e0, e1, q0, q1;
        asm("ex2.approx.f32 %0, %1;" : "=f"(e0) : "f"(zn0));
        asm("ex2.approx.f32 %0, %1;" : "=f"(e1) : "f"(zn1));
        asm("rcp.approx.f32 %0, %1;" : "=f"(q0) : "f"(1.f + e0));
        asm("rcp.approx.f32 %0, %1;" : "=f"(q1) : "f"(1.f + e1));

        m0 = fmaf(m0, DECAY, th.x * q0);
        m1 = fmaf(m1, DECAY, th.y * q1);

        const int   s0i = m0 > th.x ? 1 : 0;
        const int   s1i = m1 > th.y ? 1 : 0;
        const float sc0 = s0i ? m0 : 0.f;
        const float sc1 = s1i ? m1 : 0.f;

        // per-lane candidate; lower channel wins ties (argmax-first semantics)
        float bs; int bi;
        if (sc0 >= sc1) { bs = sc0; bi = (c0 << 1) | s0i; }
        else            { bs = sc1; bi = (c1 << 1) | s1i; }

        unsigned ub   = __float_as_uint(bs);
        unsigned key  = ((int)ub < 0) ? ~ub : (ub | 0x80000000u);
        unsigned mk   = __reduce_max_sync(0xffffffffu, key);
        unsigned cand = (key == mk) ? (unsigned)bi : 0x7fffffffu;
        const int wz  = (int)__reduce_min_sync(0xffffffffu, cand);

        const int   wc  = wz >> 1;
        const float any = (float)(wz & 1);            // winner's spike -> any_sp

        const float sn0 = (wc == c0) ? (float)s0i : 0.f;
        const float sn1 = (wc == c1) ? (float)s1i : 0.f;

        m0 = (sn0 > 0.f) ? 0.f : fmaf(-ih.x, any, m0);
        m1 = (sn1 > 0.f) ? 0.f : fmaf(-ih.y, any, m1);

        if (tx == 0) swz[ty][t] = wz;
    }
    __syncthreads();

    // store phase: reference layout (t,b,c,h,w); lanes = pixels (coalesced)
    const int obase = (b * COUT) * SPAT + spb + tx;
    const int ostep = B_SZ * COUT * SPAT;
#pragma unroll
    for (int t = 0; t < T_STEPS; t++) {
        const int w = swz[tx][t];
        out[obase + t * ostep + ty * SPAT]        = (w == ((ty << 1) | 1))        ? 1.f : 0.f;
        out[obase + t * ostep + (ty + 32) * SPAT] = (w == (((ty + 32) << 1) | 1)) ? 1.f : 0.f;
    }
}

// ---------------------------------------------------------------------------
extern "C" void kernel_launch(void* const* d_in, const int* in_sizes, int n_in,
                              void* d_out, int out_size) {
    const float* x = (const float*)d_in[0];
    const float* W = (const float*)d_in[1];
    if (n_in >= 2 && in_sizes[0] == COUT * CIN * 9) {  // defensive order swap
        const float* tmp = x; x = W; W = tmp;
    }

    dim3 cb(32, 4);
    dim3 cg(2, 4, T_STEPS * B_SZ);
    conv_kernel<<<cg, cb>>>(x, W);

    finalize_thr<<<1, N_THR>>>();

    lif_kernel<<<(B_SZ * SPAT) / 32, dim3(32, 32)>>>((float*)d_out);
}